// round 7
// baseline (speedup 1.0000x reference)
#include <cuda_runtime.h>
#include <math.h>
#include <stdint.h>

#define B_L   192
#define NVAL  325
#define NPAD  352
#define D     256
#define DPOS  64
#define KPROJ 320
#define HEADS 8
#define EDIM  32
#define BH    (B_L*HEADS)      /* 1536 */
#define NH    4
#define NB    22
#define NC    (NH*NB)          /* 88 */
#define BKTS  16
#define NS    (NH*NPAD)        /* 1408 */
#define MROWS (B_L*NPAD)       /* 67584 */

typedef unsigned long long u64;

// ---------------- PTX helpers ---------------------------------------------------
__device__ __forceinline__ u64 pack2(float x, float y) {
    u64 r; asm("mov.b64 %0,{%1,%2};" : "=l"(r) : "f"(x), "f"(y)); return r;
}
__device__ __forceinline__ void unpack2(u64 v, float& x, float& y) {
    asm("mov.b64 {%0,%1},%2;" : "=f"(x), "=f"(y) : "l"(v));
}
__device__ __forceinline__ u64 fma2(u64 a, u64 b, u64 c) {
    u64 d; asm("fma.rn.f32x2 %0,%1,%2,%3;" : "=l"(d) : "l"(a), "l"(b), "l"(c)); return d;
}
__device__ __forceinline__ uint32_t smem_u32(const void* p) {
    uint32_t a;
    asm("{ .reg .u64 t; cvta.to.shared.u64 t, %1; cvt.u32.u64 %0, t; }" : "=r"(a) : "l"(p));
    return a;
}
__device__ __forceinline__ uint32_t f2tf(float x) {
    uint32_t r; asm("cvt.rna.tf32.f32 %0,%1;" : "=r"(r) : "f"(x)); return r;
}
__device__ __forceinline__ void mma8(float* c, const uint32_t* a, const uint32_t* b) {
    asm volatile(
        "mma.sync.aligned.m16n8k8.row.col.f32.tf32.tf32.f32 "
        "{%0,%1,%2,%3},{%4,%5,%6,%7},{%8,%9},{%0,%1,%2,%3};"
        : "+f"(c[0]), "+f"(c[1]), "+f"(c[2]), "+f"(c[3])
        : "r"(a[0]), "r"(a[1]), "r"(a[2]), "r"(a[3]), "r"(b[0]), "r"(b[1]));
}
#define LDMX4(r0, r1, r2, r3, addr) \
    asm volatile("ldmatrix.sync.aligned.m8n8.x4.shared.b16 {%0,%1,%2,%3},[%4];" \
        : "=r"(r0), "=r"(r1), "=r"(r2), "=r"(r3) : "r"(addr))

// ---------------- scratch -------------------------------------------------------
__device__ __align__(16) float g_h    [MROWS*D];
__device__ __align__(16) float g_qk   [BH*NPAD*EDIM];
__device__ __align__(16) float g_v    [BH*NPAD*EDIM];
__device__ int   g_bucket [BH*NS];
__device__ int   g_sticker[BH*NS];
__device__ __align__(16) float g_o    [BH*NH*NPAD*EDIM];
__device__ float g_lse  [BH*NH*NPAD];
__device__ __align__(16) float g_hcomb[MROWS*D];

// -------- scalar 128x128 SGEMM, BK=8, 8x8/thread 2x2 quadrants, FFMA2 ----------
// (bit-identical math to the R4 kernel that passed at rel_err 3.41e-7)
// MODE 0: h = [x|ste] @ w_proj + b_proj (K=320) -> g_h (pad rows 0)
// MODE 1: qk = g_h @ w_qk (K=256)              -> g_qk head-scatter
template<int MODE>
__global__ __launch_bounds__(256, 2)
void gemm_k(const float* __restrict__ P0, const float* __restrict__ P1,
            const float* __restrict__ W0, const float* __restrict__ bias)
{
    constexpr int BM = 128, BN = 128, BK = 8;
    constexpr int KDIM = (MODE == 0) ? KPROJ : 256;
    constexpr int NT   = KDIM / BK;
    constexpr int LDA  = BM + 4;

    __shared__ float As[2][BK][LDA];
    __shared__ float Bs[2][BK][BN];

    const int tid = threadIdx.x;
    const int bm  = blockIdx.x * BM;
    const int bn  = blockIdx.y * BN;

    const int arow  = tid >> 1;
    const int akoff = (tid & 1) * 4;
    const int bk    = tid >> 5;
    const int bcol  = (tid & 31) * 4;

    const int r = bm + arow;
    long baseA, baseS = 0;
    bool validA = true;
    if (MODE == 0) {
        int b_l = r / NPAD;
        int n   = r - b_l * NPAD;
        validA  = (n < NVAL);
        long rr = (long)b_l * NVAL + n;
        baseA = rr * D;
        baseS = rr * DPOS;
    } else {
        baseA = (long)r * D;
    }

    float4 aReg, bReg;

    auto load_gmem = [&](int kt) {
        int kk = kt + akoff;
        if (MODE == 0) {
            if (!validA) aReg = make_float4(0.f, 0.f, 0.f, 0.f);
            else if (kk < D) aReg = *(const float4*)(P0 + baseA + kk);
            else             aReg = *(const float4*)(P1 + baseS + (kk - D));
        } else {
            aReg = *(const float4*)(g_h + baseA + kk);
        }
        bReg = *(const float4*)(W0 + (long)(kt + bk) * D + bn + bcol);
    };
    auto store_smem = [&](int buf) {
        As[buf][akoff + 0][arow] = aReg.x;
        As[buf][akoff + 1][arow] = aReg.y;
        As[buf][akoff + 2][arow] = aReg.z;
        As[buf][akoff + 3][arow] = aReg.w;
        *(float4*)(&Bs[buf][bk][bcol]) = bReg;
    };

    const int ty = tid >> 4;
    const int tx = tid & 15;

    u64 acc2[2][2][4][2];
#pragma unroll
    for (int gi = 0; gi < 2; gi++)
#pragma unroll
        for (int gj = 0; gj < 2; gj++)
#pragma unroll
            for (int i = 0; i < 4; i++) {
                acc2[gi][gj][i][0] = 0ULL;
                acc2[gi][gj][i][1] = 0ULL;
            }

    load_gmem(0);
    store_smem(0);
    __syncthreads();

    int buf = 0;
    for (int t = 0; t < NT; ++t) {
        if (t + 1 < NT) load_gmem((t + 1) * BK);
#pragma unroll
        for (int k = 0; k < BK; k++) {
            float4 a0 = *(const float4*)(&As[buf][k][ty * 4]);
            float4 a1 = *(const float4*)(&As[buf][k][64 + ty * 4]);
            float4 b0 = *(const float4*)(&Bs[buf][k][tx * 4]);
            float4 b1 = *(const float4*)(&Bs[buf][k][64 + tx * 4]);
            u64 bp[2][2] = {{pack2(b0.x, b0.y), pack2(b0.z, b0.w)},
                            {pack2(b1.x, b1.y), pack2(b1.z, b1.w)}};
            float av[2][4] = {{a0.x, a0.y, a0.z, a0.w}, {a1.x, a1.y, a1.z, a1.w}};
#pragma unroll
            for (int gi = 0; gi < 2; gi++)
#pragma unroll
                for (int i = 0; i < 4; i++) {
                    u64 ap = pack2(av[gi][i], av[gi][i]);
#pragma unroll
                    for (int gj = 0; gj < 2; gj++) {
                        acc2[gi][gj][i][0] = fma2(ap, bp[gj][0], acc2[gi][gj][i][0]);
                        acc2[gi][gj][i][1] = fma2(ap, bp[gj][1], acc2[gi][gj][i][1]);
                    }
                }
        }
        if (t + 1 < NT) {
            store_smem(buf ^ 1);
            __syncthreads();
            buf ^= 1;
        }
    }

#pragma unroll
    for (int gi = 0; gi < 2; gi++)
#pragma unroll
    for (int i = 0; i < 4; i++) {
        int ro = bm + gi * 64 + ty * 4 + i;
#pragma unroll
        for (int gj = 0; gj < 2; gj++) {
            int cb = bn + gj * 64 + tx * 4;
            float c0, c1, c2, c3;
            unpack2(acc2[gi][gj][i][0], c0, c1);
            unpack2(acc2[gi][gj][i][1], c2, c3);

            if (MODE == 0) {
                int n = ro % NPAD;
                float4 v;
                if (n < NVAL)
                    v = make_float4(c0 + bias[cb + 0], c1 + bias[cb + 1],
                                    c2 + bias[cb + 2], c3 + bias[cb + 3]);
                else
                    v = make_float4(0.f, 0.f, 0.f, 0.f);
                *(float4*)(g_h + (long)ro * D + cb) = v;
            } else {
                int b_l = ro / NPAD;
                int n   = ro - b_l * NPAD;
                int head = cb >> 5, e = cb & 31;
                float* dst = g_qk + ((long)((b_l << 3) + head) * NPAD + n) * EDIM + e;
                *(float4*)(dst) = make_float4(c0, c1, c2, c3);
            }
        }
    }
}

// ---------------- 3xTF32 mma.sync GEMM (smooth path: v, out) --------------------
// MODE 1: g_h @ w_v -> g_v head-scatter          KT=256
// MODE 2: g_hcomb @ w_out + b_out -> out (n<NVAL) KT=256
template<int MODE>
__global__ __launch_bounds__(256)
void gemm_tf(const float* __restrict__ W0, const float* __restrict__ bias,
             float* __restrict__ Cout)
{
    constexpr int KT  = 256;
    constexpr int NT  = KT / 16;
    constexpr int NSP = 2;
    constexpr int NSEG = 3;
    constexpr int ABYTES = 128 * 80;
    constexpr int BBYTES = 16 * 544;
    constexpr int BUFSZ  = NSP * (ABYTES + BBYTES);
    constexpr int SA[3] = {0, 0, 1};
    constexpr int SB[3] = {0, 1, 0};

    extern __shared__ __align__(16) char smem[];
    const int tid  = threadIdx.x;
    const int wid  = tid >> 5, lane = tid & 31;
    const int g    = lane >> 2, tig = lane & 3;
    const int wm   = wid >> 2, wn = wid & 3;
    const int bm   = blockIdx.x * 128;
    const int bnloc = blockIdx.y * 128;

    int arow[2], af4[2];
    long abx[2];
#pragma unroll
    for (int i = 0; i < 2; i++) {
        int idx = i * 256 + tid;
        arow[i] = idx >> 2;
        af4[i]  = idx & 3;
        abx[i] = (long)(bm + arow[i]) * D;
    }
    int bk_[2], bn_[2];
#pragma unroll
    for (int i = 0; i < 2; i++) {
        int idx = i * 256 + tid;
        bk_[i] = idx >> 5;
        bn_[i] = (idx & 31) * 4;
    }

    float4 av[2], bv[2];
    auto load_gmem = [&](int kt) {
#pragma unroll
        for (int i = 0; i < 2; i++) {
            int kk = kt + af4[i] * 4;
            av[i] = (MODE == 1) ? *(const float4*)(g_h + abx[i] + kk)
                                : *(const float4*)(g_hcomb + abx[i] + kk);
            bv[i] = *(const float4*)(W0 + (long)(kt + bk_[i]) * D + bnloc + bn_[i]);
        }
    };
    auto split_sts = [&](int buf) {
#pragma unroll
        for (int i = 0; i < 2; i++) {
            float va[4] = {av[i].x, av[i].y, av[i].z, av[i].w};
            float vb[4] = {bv[i].x, bv[i].y, bv[i].z, bv[i].w};
            uint32_t ta[2][4], tb[2][4];
#pragma unroll
            for (int c = 0; c < 4; c++) {
                float v = va[c];
                ta[0][c] = f2tf(v); v -= __uint_as_float(ta[0][c]);
                ta[1][c] = f2tf(v);
                v = vb[c];
                tb[0][c] = f2tf(v); v -= __uint_as_float(tb[0][c]);
                tb[1][c] = f2tf(v);
            }
#pragma unroll
            for (int sp = 0; sp < NSP; sp++) {
                *(uint4*)(smem + buf * BUFSZ + sp * ABYTES + arow[i] * 80 + af4[i] * 16) =
                    make_uint4(ta[sp][0], ta[sp][1], ta[sp][2], ta[sp][3]);
                *(uint4*)(smem + buf * BUFSZ + NSP * ABYTES + sp * BBYTES +
                          bk_[i] * 544 + bn_[i] * 4) =
                    make_uint4(tb[sp][0], tb[sp][1], tb[sp][2], tb[sp][3]);
            }
        }
    };

    float acc[4][4][4];
#pragma unroll
    for (int mf = 0; mf < 4; mf++)
#pragma unroll
        for (int nf = 0; nf < 4; nf++)
#pragma unroll
            for (int q = 0; q < 4; q++) acc[mf][nf][q] = 0.f;

    const uint32_t sbase = smem_u32(smem);
    const int arl  = (lane < 16) ? lane : lane - 16;
    const int ac16 = (lane < 16) ? 0 : 16;

    auto compute = [&](int buf) {
#pragma unroll
        for (int k8 = 0; k8 < 2; k8++) {
            const int kc = k8 * 8;
            uint32_t a[NSP][4][4], b[NSP][4][2];
#pragma unroll
            for (int sp = 0; sp < NSP; sp++) {
                uint32_t ab = sbase + buf * BUFSZ + sp * ABYTES +
                              (wm * 64 + arl) * 80 + kc * 4 + ac16;
#pragma unroll
                for (int mf = 0; mf < 4; mf++)
                    LDMX4(a[sp][mf][0], a[sp][mf][1], a[sp][mf][2], a[sp][mf][3],
                          ab + mf * (16 * 80));
                const uint32_t* Bp =
                    (const uint32_t*)(smem + buf * BUFSZ + NSP * ABYTES + sp * BBYTES);
#pragma unroll
                for (int nf = 0; nf < 4; nf++) {
                    int nn0 = wn * 32 + nf * 8 + g;
                    b[sp][nf][0] = Bp[(kc + tig) * 136 + nn0];
                    b[sp][nf][1] = Bp[(kc + tig + 4) * 136 + nn0];
                }
            }
#pragma unroll
            for (int s = 0; s < NSEG; s++)
#pragma unroll
                for (int mf = 0; mf < 4; mf++)
#pragma unroll
                    for (int nf = 0; nf < 4; nf++)
                        mma8(acc[mf][nf], a[SA[s]][mf], b[SB[s]][nf]);
        }
    };

    load_gmem(0);
    split_sts(0);
    __syncthreads();
    int buf = 0;
    for (int t = 0; t < NT; t++) {
        if (t + 1 < NT) load_gmem((t + 1) * 16);
        compute(buf);
        if (t + 1 < NT) {
            split_sts(buf ^ 1);
            __syncthreads();
            buf ^= 1;
        }
    }

#pragma unroll
    for (int mf = 0; mf < 4; mf++)
#pragma unroll
    for (int nf = 0; nf < 4; nf++) {
        int col = bnloc + wn * 32 + nf * 8 + tig * 2;
#pragma unroll
        for (int half = 0; half < 2; half++) {
            int row = bm + wm * 64 + mf * 16 + g + half * 8;
            float v0 = acc[mf][nf][half * 2 + 0];
            float v1 = acc[mf][nf][half * 2 + 1];
            int b_l = row / NPAD, n = row - b_l * NPAD;
            if (MODE == 1) {
                int head = col >> 5, e = col & 31;
                float* dst = g_v + ((long)((b_l << 3) + head) * NPAD + n) * EDIM + e;
                *(float2*)dst = make_float2(v0, v1);
            } else {
                if (n < NVAL) {
                    long off = ((long)b_l * NVAL + n) * D + col;
                    *(float2*)(Cout + off) = make_float2(v0 + bias[col], v1 + bias[col + 1]);
                }
            }
        }
    }
}

// ---------------- hashing: rot = qk @ rotations, argmax over [rot,-rot] -------
__global__ __launch_bounds__(256)
void hash_kernel(const float* __restrict__ rot)
{
    __shared__ u64 srot2[EDIM][NH][6];
    int tid = threadIdx.x;
    for (int i = tid; i < EDIM * NH * 6; i += blockDim.x) {
        int e  = i / (NH * 6);
        int h  = (i / 6) % NH;
        int rr = i % 6;
        int r0 = 2 * rr, r1 = 2 * rr + 1;
        float xv = (r0 < NB / 2) ? rot[(e * NH + h) * (NB / 2) + r0] : 0.f;
        float yv = (r1 < NB / 2) ? rot[(e * NH + h) * (NB / 2) + r1] : 0.f;
        srot2[e][h][rr] = pack2(xv, yv);
    }
    __syncthreads();

    int gid = blockIdx.x * blockDim.x + tid;
    if (gid >= BH * NPAD) return;
    int bh = gid / NPAD;
    int n  = gid - bh * NPAD;

    float q[EDIM];
    const float* qp = &g_qk[(long)(bh * NPAD + n) * EDIM];
#pragma unroll
    for (int e = 0; e < EDIM; e += 4) {
        float4 t = *(const float4*)(qp + e);
        q[e] = t.x; q[e + 1] = t.y; q[e + 2] = t.z; q[e + 3] = t.w;
    }

    for (int h = 0; h < NH; h++) {
        u64 s2[6];
#pragma unroll
        for (int rr = 0; rr < 6; rr++) s2[rr] = 0ULL;
#pragma unroll
        for (int e = 0; e < EDIM; e++) {
            u64 qq = pack2(q[e], q[e]);
#pragma unroll
            for (int rr = 0; rr < 6; rr++)
                s2[rr] = fma2(qq, srot2[e][h][rr], s2[rr]);
        }
        float rv[12];
#pragma unroll
        for (int rr = 0; rr < 6; rr++) unpack2(s2[rr], rv[2 * rr], rv[2 * rr + 1]);

        float best = rv[0];
        int bi = 0;
#pragma unroll
        for (int r = 1; r < NB / 2; r++)
            if (rv[r] > best) { best = rv[r]; bi = r; }
#pragma unroll
        for (int r = 0; r < NB / 2; r++)
            if (-rv[r] > best) { best = -rv[r]; bi = r + NB / 2; }
        g_bucket[bh * NS + h * NPAD + n] = bi + h * NB;
    }
}

// ---------------- stable counting sort per bh (88 buckets, 1408 items) --------
__global__ __launch_bounds__(128)
void sort_kernel()
{
    const int bh  = blockIdx.x;
    const int tid = threadIdx.x;

    __shared__ unsigned short hist[128][89];
    __shared__ int sbuck[NS];
    __shared__ int base[NC];
    __shared__ int tot[NC];

    for (int i = tid; i < NS; i += 128) sbuck[i] = g_bucket[bh * NS + i];
    for (int b = 0; b < NC; b++) hist[tid][b] = 0;
    __syncthreads();

#pragma unroll
    for (int k = 0; k < NS / 128; k++) {
        int i = tid * (NS / 128) + k;
        hist[tid][sbuck[i]]++;
    }
    __syncthreads();

    if (tid < NC) {
        int s = 0;
        for (int t = 0; t < 128; t++) s += hist[t][tid];
        tot[tid] = s;
    }
    __syncthreads();
    if (tid == 0) {
        int run = 0;
        for (int b = 0; b < NC; b++) { base[b] = run; run += tot[b]; }
    }
    __syncthreads();
    if (tid < NC) {
        int run = base[tid];
        for (int t = 0; t < 128; t++) {
            int c = hist[t][tid];
            hist[t][tid] = (unsigned short)run;
            run += c;
        }
    }
    __syncthreads();

#pragma unroll
    for (int k = 0; k < NS / 128; k++) {
        int i = tid * (NS / 128) + k;
        int b = sbuck[i];
        int pos = hist[tid][b]++;
        g_sticker[bh * NS + pos] = i;
    }
}

// ---------------- chunked attention: 16 queries x 32 keys per block -----------
__global__ __launch_bounds__(512)
void attn_kernel()
{
    const int c  = blockIdx.x;
    const int bh = blockIdx.y;

    __shared__ float kq[32][33];
    __shared__ float vv[32][33];
    __shared__ float rn[32];
    __shared__ int   nn[32];
    __shared__ int   hh[32];

    const int tid  = threadIdx.x;
    const int warp = tid >> 5;
    const int lane = tid & 31;

    if (tid < 32) {
        int cj   = (tid < BKTS) ? c : (c + NC - 1) % NC;
        int slot = cj * BKTS + (tid & (BKTS - 1));
        int item = g_sticker[bh * NS + slot];
        int n    = item % NPAD;
        nn[tid] = n;
        hh[tid] = item / NPAD;
    }
    __syncthreads();

    for (int idx = tid; idx < 32 * EDIM; idx += 512) {
        int j = idx >> 5, e = idx & 31;
        long off = (long)(bh * NPAD + nn[j]) * EDIM + e;
        kq[j][e] = g_qk[off];
        vv[j][e] = g_v[off];
    }
    __syncthreads();

    if (tid < 32) {
        float s = 0.f;
#pragma unroll
        for (int e = 0; e < EDIM; e++) { float x = kq[tid][e]; s += x * x; }
        s = sqrtf(s);
        rn[tid] = 1.0f / fmaxf(s, 1e-12f);
    }
    __syncthreads();

    const int i = warp;
    const int j = lane;

    float d = 0.f;
#pragma unroll
    for (int e = 0; e < EDIM; e++) d += kq[i][e] * kq[j][e];
    d = d * rn[j] * 0.17677669529663687f;
    if (nn[i] == nn[j]) d = -50000.0f;

    float m = d;
#pragma unroll
    for (int o = 16; o > 0; o >>= 1) m = fmaxf(m, __shfl_xor_sync(0xffffffffu, m, o));
    float ex = expf(d - m);
    float sum = ex;
#pragma unroll
    for (int o = 16; o > 0; o >>= 1) sum += __shfl_xor_sync(0xffffffffu, sum, o);
    float lse = m + logf(sum);
    float p = ex / sum;

    float accv = 0.f;
#pragma unroll
    for (int jj = 0; jj < 32; jj++) {
        float pj = __shfl_sync(0xffffffffu, p, jj);
        accv += pj * vv[jj][lane];
    }

    int n_i = nn[i], h_i = hh[i];
    g_o[((long)(bh * NH + h_i) * NPAD + n_i) * EDIM + lane] = accv;
    if (lane == 0) g_lse[(bh * NH + h_i) * NPAD + n_i] = lse;
}

// ---------------- combine hashes: softmax over per-hash lse -------------------
__global__ __launch_bounds__(256)
void combine_kernel()
{
    int gid  = blockIdx.x * blockDim.x + threadIdx.x;
    int wid  = gid >> 5;
    int lane = gid & 31;
    if (wid >= BH * NPAD) return;
    int bh = wid / NPAD;
    int n  = wid - bh * NPAD;

    float l0 = g_lse[(bh * NH + 0) * NPAD + n];
    float l1 = g_lse[(bh * NH + 1) * NPAD + n];
    float l2 = g_lse[(bh * NH + 2) * NPAD + n];
    float l3 = g_lse[(bh * NH + 3) * NPAD + n];
    float m = fmaxf(fmaxf(l0, l1), fmaxf(l2, l3));
    float e0 = expf(l0 - m), e1 = expf(l1 - m), e2 = expf(l2 - m), e3 = expf(l3 - m);
    float inv = 1.0f / (e0 + e1 + e2 + e3);

    float acc =
        e0 * inv * g_o[((long)(bh * NH + 0) * NPAD + n) * EDIM + lane] +
        e1 * inv * g_o[((long)(bh * NH + 1) * NPAD + n) * EDIM + lane] +
        e2 * inv * g_o[((long)(bh * NH + 2) * NPAD + n) * EDIM + lane] +
        e3 * inv * g_o[((long)(bh * NH + 3) * NPAD + n) * EDIM + lane];

    int b_l = bh >> 3, head = bh & 7;
    g_hcomb[(long)(b_l * NPAD + n) * D + head * EDIM + lane] = acc;
}

// ---------------- launch --------------------------------------------------------
extern "C" void kernel_launch(void* const* d_in, const int* in_sizes, int n_in,
                              void* d_out, int out_size)
{
    const float* x      = (const float*)d_in[0];
    const float* ste    = (const float*)d_in[1];
    const float* w_proj = (const float*)d_in[2];
    const float* b_proj = (const float*)d_in[3];
    const float* w_qk   = (const float*)d_in[4];
    const float* w_v    = (const float*)d_in[5];
    const float* w_out  = (const float*)d_in[6];
    const float* b_out  = (const float*)d_in[7];
    const float* rots   = (const float*)d_in[8];
    float* out = (float*)d_out;

    constexpr int SM3 = 2 * 2 * (128 * 80 + 16 * 544);  // 75776 B

    cudaFuncSetAttribute(gemm_tf<1>, cudaFuncAttributeMaxDynamicSharedMemorySize, SM3);
    cudaFuncSetAttribute(gemm_tf<2>, cudaFuncAttributeMaxDynamicSharedMemorySize, SM3);

    // 1. projection (scalar fp32 — bucket-critical)
    gemm_k<0><<<dim3(MROWS / 128, 2), 256>>>(x, ste, w_proj, b_proj);
    // 2a. qk (scalar fp32 — bucket-critical); 2b. v (3xTF32, smooth)
    gemm_k<1><<<dim3(MROWS / 128, 2), 256>>>(nullptr, nullptr, w_qk, nullptr);
    gemm_tf<1><<<dim3(MROWS / 128, 2), 256, SM3>>>(w_v, nullptr, nullptr);
    // 3-6. LSH pipeline
    hash_kernel<<<(BH * NPAD + 255) / 256, 256>>>(rots);
    sort_kernel<<<BH, 128>>>();
    attn_kernel<<<dim3(NC, BH), 512>>>();
    combine_kernel<<<(BH * NPAD * 32) / 256, 256>>>();
    // 7. output projection (3xTF32, smooth)
    gemm_tf<2><<<dim3(MROWS / 128, 2), 256, SM3>>>(w_out, b_out, out);
}

// round 9
// speedup vs baseline: 1.1582x; 1.1582x over previous
#include <cuda_runtime.h>
#include <math.h>
#include <stdint.h>

#define B_L   192
#define NVAL  325
#define NPAD  352
#define D     256
#define DPOS  64
#define KPROJ 320
#define HEADS 8
#define EDIM  32
#define BH    (B_L*HEADS)      /* 1536 */
#define NH    4
#define NB    22
#define NC    (NH*NB)          /* 88 */
#define BKTS  16
#define NS    (NH*NPAD)        /* 1408 */
#define MROWS (B_L*NPAD)       /* 67584 */
#define MVAL  (B_L*NVAL)       /* 62400 */
#define GRIDM 488              /* ceil(62400/128) */

typedef unsigned long long u64;

__device__ __forceinline__ u64 pack2(float x, float y) {
    u64 r; asm("mov.b64 %0,{%1,%2};" : "=l"(r) : "f"(x), "f"(y)); return r;
}
__device__ __forceinline__ void unpack2(u64 v, float& x, float& y) {
    asm("mov.b64 {%0,%1},%2;" : "=f"(x), "=f"(y) : "l"(v));
}
__device__ __forceinline__ u64 fma2(u64 a, u64 b, u64 c) {
    u64 d; asm("fma.rn.f32x2 %0,%1,%2,%3;" : "=l"(d) : "l"(a), "l"(b), "l"(c)); return d;
}

// ---------------- scratch -------------------------------------------------------
__device__ __align__(16) float g_h    [MROWS*D];
__device__ __align__(16) float g_qk   [BH*NPAD*EDIM];
__device__ __align__(16) float g_v    [BH*NPAD*EDIM];
__device__ int   g_bucket [BH*NS];
__device__ int   g_sticker[BH*NS];
__device__ __align__(16) float g_o    [BH*NH*NPAD*EDIM];
__device__ float g_lse  [BH*NH*NPAD];
__device__ __align__(16) float g_hcomb[MROWS*D];

// -------- 128x128 SGEMM over VALID rows only, BK=8, 8x8/thread quadrants, FFMA2
// (inner accumulation bit-identical to the R4 kernel that passed at 3.414894e-07)
// MODE 0: h = [x|ste] @ w_proj + b_proj (K=320) -> g_h (valid rows)
// MODE 1: [qk|v] = g_h @ [w_qk|w_v] (K=256, N=512) -> g_qk/g_v head-scatter
// MODE 2: out = g_hcomb @ w_out + b_out (K=256) -> d_out
template<int MODE>
__global__ __launch_bounds__(256, 2)
void gemm_k(const float* __restrict__ P0, const float* __restrict__ P1,
            const float* __restrict__ W0, const float* __restrict__ W1,
            const float* __restrict__ bias, float* __restrict__ Cout)
{
    constexpr int BM = 128, BN = 128, BK = 8;
    constexpr int KDIM = (MODE == 0) ? KPROJ : 256;
    constexpr int NT   = KDIM / BK;
    constexpr int LDA  = BM + 4;

    __shared__ float As[2][BK][LDA];
    __shared__ float Bs[2][BK][BN];

    const int tid = threadIdx.x;
    const int bm  = blockIdx.x * BM;
    const int bn  = blockIdx.y * BN;

    const int arow  = tid >> 1;
    const int akoff = (tid & 1) * 4;
    const int bk    = tid >> 5;
    const int bcol  = (tid & 31) * 4;

    const int r = bm + arow;
    const bool validA = (r < MVAL);
    long baseA = 0, baseS = 0;
    if (MODE == 0) {
        baseA = (long)r * D;          // x is contiguous over valid rows
        baseS = (long)r * DPOS;
    } else {
        int rr = validA ? r : 0;
        int b_l = rr / NVAL, n = rr - b_l * NVAL;
        baseA = ((long)b_l * NPAD + n) * D;
    }

    const float* Wp;
    int wbase;
    if (MODE == 1 && bn >= 256) { Wp = W1; wbase = bn - 256; }
    else                         { Wp = W0; wbase = bn; }

    float4 aReg, bReg;

    auto load_gmem = [&](int kt) {
        int kk = kt + akoff;
        if (MODE == 0) {
            if (!validA) aReg = make_float4(0.f, 0.f, 0.f, 0.f);
            else if (kk < D) aReg = *(const float4*)(P0 + baseA + kk);
            else             aReg = *(const float4*)(P1 + baseS + (kk - D));
        } else if (MODE == 1) {
            aReg = *(const float4*)(g_h + baseA + kk);
        } else {
            aReg = *(const float4*)(g_hcomb + baseA + kk);
        }
        bReg = *(const float4*)(Wp + (long)(kt + bk) * D + wbase + bcol);
    };
    auto store_smem = [&](int buf) {
        As[buf][akoff + 0][arow] = aReg.x;
        As[buf][akoff + 1][arow] = aReg.y;
        As[buf][akoff + 2][arow] = aReg.z;
        As[buf][akoff + 3][arow] = aReg.w;
        *(float4*)(&Bs[buf][bk][bcol]) = bReg;
    };

    const int ty = tid >> 4;
    const int tx = tid & 15;

    u64 acc2[2][2][4][2];
#pragma unroll
    for (int gi = 0; gi < 2; gi++)
#pragma unroll
        for (int gj = 0; gj < 2; gj++)
#pragma unroll
            for (int i = 0; i < 4; i++) {
                acc2[gi][gj][i][0] = 0ULL;
                acc2[gi][gj][i][1] = 0ULL;
            }

    load_gmem(0);
    store_smem(0);
    __syncthreads();

    int buf = 0;
    for (int t = 0; t < NT; ++t) {
        if (t + 1 < NT) load_gmem((t + 1) * BK);
#pragma unroll
        for (int k = 0; k < BK; k++) {
            float4 a0 = *(const float4*)(&As[buf][k][ty * 4]);
            float4 a1 = *(const float4*)(&As[buf][k][64 + ty * 4]);
            float4 b0 = *(const float4*)(&Bs[buf][k][tx * 4]);
            float4 b1 = *(const float4*)(&Bs[buf][k][64 + tx * 4]);
            u64 bp[2][2] = {{pack2(b0.x, b0.y), pack2(b0.z, b0.w)},
                            {pack2(b1.x, b1.y), pack2(b1.z, b1.w)}};
            float av[2][4] = {{a0.x, a0.y, a0.z, a0.w}, {a1.x, a1.y, a1.z, a1.w}};
#pragma unroll
            for (int gi = 0; gi < 2; gi++)
#pragma unroll
                for (int i = 0; i < 4; i++) {
                    u64 ap = pack2(av[gi][i], av[gi][i]);
#pragma unroll
                    for (int gj = 0; gj < 2; gj++) {
                        acc2[gi][gj][i][0] = fma2(ap, bp[gj][0], acc2[gi][gj][i][0]);
                        acc2[gi][gj][i][1] = fma2(ap, bp[gj][1], acc2[gi][gj][i][1]);
                    }
                }
        }
        if (t + 1 < NT) {
            store_smem(buf ^ 1);
            __syncthreads();
            buf ^= 1;
        }
    }

    // ---- epilogue (valid rows only) ----
#pragma unroll
    for (int gi = 0; gi < 2; gi++)
#pragma unroll
    for (int i = 0; i < 4; i++) {
        int ro = bm + gi * 64 + ty * 4 + i;
        if (ro >= MVAL) continue;
#pragma unroll
        for (int gj = 0; gj < 2; gj++) {
            int cb = bn + gj * 64 + tx * 4;
            float c0, c1, c2, c3;
            unpack2(acc2[gi][gj][i][0], c0, c1);
            unpack2(acc2[gi][gj][i][1], c2, c3);

            if (MODE == 0) {
                int b_l = ro / NVAL, n = ro - b_l * NVAL;
                *(float4*)(g_h + ((long)b_l * NPAD + n) * D + cb) =
                    make_float4(c0 + bias[cb + 0], c1 + bias[cb + 1],
                                c2 + bias[cb + 2], c3 + bias[cb + 3]);
            } else if (MODE == 1) {
                int b_l = ro / NVAL, n = ro - b_l * NVAL;
                int cc = cb;
                float* dst;
                if (cc < D) { int head = cc >> 5; int e = cc & 31;
                    dst = g_qk + ((long)((b_l << 3) + head) * NPAD + n) * EDIM + e; }
                else { cc -= D; int head = cc >> 5; int e = cc & 31;
                    dst = g_v  + ((long)((b_l << 3) + head) * NPAD + n) * EDIM + e; }
                *(float4*)(dst) = make_float4(c0, c1, c2, c3);
            } else {
                *(float4*)(Cout + (long)ro * D + cb) =
                    make_float4(c0 + bias[cb + 0], c1 + bias[cb + 1],
                                c2 + bias[cb + 2], c3 + bias[cb + 3]);
            }
        }
    }
}

// ---------------- zero-fill pad-row qk/v (h pad rows are exactly zero) ---------
__global__ __launch_bounds__(256)
void zero_pad_qkv()
{
    int gid = blockIdx.x * 256 + threadIdx.x;
    const int total = BH * (NPAD - NVAL) * EDIM;  // 1,327,104
    if (gid >= total) return;
    int e  = gid & 31;
    int t  = gid >> 5;
    int pi = t % (NPAD - NVAL);
    int bh = t / (NPAD - NVAL);
    long off = ((long)bh * NPAD + NVAL + pi) * EDIM + e;
    g_qk[off] = 0.f;
    g_v[off]  = 0.f;
}

// ---------------- hashing: rot = qk @ rotations, argmax over [rot,-rot] -------
__global__ __launch_bounds__(256)
void hash_kernel(const float* __restrict__ rot)
{
    __shared__ u64 srot2[EDIM][NH][6];
    int tid = threadIdx.x;
    for (int i = tid; i < EDIM * NH * 6; i += blockDim.x) {
        int e  = i / (NH * 6);
        int h  = (i / 6) % NH;
        int rr = i % 6;
        int r0 = 2 * rr, r1 = 2 * rr + 1;
        float xv = (r0 < NB / 2) ? rot[(e * NH + h) * (NB / 2) + r0] : 0.f;
        float yv = (r1 < NB / 2) ? rot[(e * NH + h) * (NB / 2) + r1] : 0.f;
        srot2[e][h][rr] = pack2(xv, yv);
    }
    __syncthreads();

    int gid = blockIdx.x * blockDim.x + tid;
    if (gid >= BH * NPAD) return;
    int bh = gid / NPAD;
    int n  = gid - bh * NPAD;

    float q[EDIM];
    const float* qp = &g_qk[(long)(bh * NPAD + n) * EDIM];
#pragma unroll
    for (int e = 0; e < EDIM; e += 4) {
        float4 t = *(const float4*)(qp + e);
        q[e] = t.x; q[e + 1] = t.y; q[e + 2] = t.z; q[e + 3] = t.w;
    }

    for (int h = 0; h < NH; h++) {
        u64 s2[6];
#pragma unroll
        for (int rr = 0; rr < 6; rr++) s2[rr] = 0ULL;
#pragma unroll
        for (int e = 0; e < EDIM; e++) {
            u64 qq = pack2(q[e], q[e]);
#pragma unroll
            for (int rr = 0; rr < 6; rr++)
                s2[rr] = fma2(qq, srot2[e][h][rr], s2[rr]);
        }
        float rv[12];
#pragma unroll
        for (int rr = 0; rr < 6; rr++) unpack2(s2[rr], rv[2 * rr], rv[2 * rr + 1]);

        float best = rv[0];
        int bi = 0;
#pragma unroll
        for (int r = 1; r < NB / 2; r++)
            if (rv[r] > best) { best = rv[r]; bi = r; }
#pragma unroll
        for (int r = 0; r < NB / 2; r++)
            if (-rv[r] > best) { best = -rv[r]; bi = r + NB / 2; }
        g_bucket[bh * NS + h * NPAD + n] = bi + h * NB;
    }
}

// ---------------- stable counting sort per bh (88 buckets, 1408 items) --------
__global__ __launch_bounds__(128)
void sort_kernel()
{
    const int bh  = blockIdx.x;
    const int tid = threadIdx.x;

    __shared__ unsigned short hist[128][89];
    __shared__ int sbuck[NS];
    __shared__ int base[NC];
    __shared__ int tot[NC];

    for (int i = tid; i < NS; i += 128) sbuck[i] = g_bucket[bh * NS + i];
    for (int b = 0; b < NC; b++) hist[tid][b] = 0;
    __syncthreads();

#pragma unroll
    for (int k = 0; k < NS / 128; k++) {
        int i = tid * (NS / 128) + k;
        hist[tid][sbuck[i]]++;
    }
    __syncthreads();

    if (tid < NC) {
        int s = 0;
        for (int t = 0; t < 128; t++) s += hist[t][tid];
        tot[tid] = s;
    }
    __syncthreads();
    if (tid == 0) {
        int run = 0;
        for (int b = 0; b < NC; b++) { base[b] = run; run += tot[b]; }
    }
    __syncthreads();
    if (tid < NC) {
        int run = base[tid];
        for (int t = 0; t < 128; t++) {
            int c = hist[t][tid];
            hist[t][tid] = (unsigned short)run;
            run += c;
        }
    }
    __syncthreads();

#pragma unroll
    for (int k = 0; k < NS / 128; k++) {
        int i = tid * (NS / 128) + k;
        int b = sbuck[i];
        int pos = hist[tid][b]++;
        g_sticker[bh * NS + pos] = i;
    }
}

// ---------------- chunked attention: 16 queries x 32 keys per block -----------
// dots/norms use f32x2 e-pairs (smooth path — reorder-safe per R7)
__global__ __launch_bounds__(512)
void attn_kernel()
{
    const int c  = blockIdx.x;
    const int bh = blockIdx.y;

    __shared__ __align__(8) float kq[32][34];
    __shared__ __align__(8) float vv[32][34];
    __shared__ float rn[32];
    __shared__ int   nn[32];
    __shared__ int   hh[32];

    const int tid  = threadIdx.x;
    const int warp = tid >> 5;
    const int lane = tid & 31;

    if (tid < 32) {
        int cj   = (tid < BKTS) ? c : (c + NC - 1) % NC;
        int slot = cj * BKTS + (tid & (BKTS - 1));
        int item = g_sticker[bh * NS + slot];
        int n    = item % NPAD;
        nn[tid] = n;
        hh[tid] = item / NPAD;
    }
    __syncthreads();

    for (int idx = tid; idx < 32 * EDIM; idx += 512) {
        int j = idx >> 5, e = idx & 31;
        long off = (long)(bh * NPAD + nn[j]) * EDIM + e;
        kq[j][e] = g_qk[off];
        vv[j][e] = g_v[off];
    }
    __syncthreads();

    if (tid < 32) {
        u64 s2 = 0ULL;
#pragma unroll
        for (int e2 = 0; e2 < EDIM / 2; e2++) {
            u64 kk = *(const u64*)(&kq[tid][2 * e2]);
            s2 = fma2(kk, kk, s2);
        }
        float sa, sb; unpack2(s2, sa, sb);
        float s = sqrtf(sa + sb);
        rn[tid] = 1.0f / fmaxf(s, 1e-12f);
    }
    __syncthreads();

    const int i = warp;
    const int j = lane;

    u64 d2 = 0ULL;
#pragma unroll
    for (int e2 = 0; e2 < EDIM / 2; e2++) {
        u64 qa = *(const u64*)(&kq[i][2 * e2]);   // broadcast
        u64 kb = *(const u64*)(&kq[j][2 * e2]);   // per-lane, conflict-free
        d2 = fma2(qa, kb, d2);
    }
    float dl, dh; unpack2(d2, dl, dh);
    float d = (dl + dh) * rn[j] * 0.17677669529663687f;
    if (nn[i] == nn[j]) d = -50000.0f;

    float m = d;
#pragma unroll
    for (int o = 16; o > 0; o >>= 1) m = fmaxf(m, __shfl_xor_sync(0xffffffffu, m, o));
    float ex = expf(d - m);
    float sum = ex;
#pragma unroll
    for (int o = 16; o > 0; o >>= 1) sum += __shfl_xor_sync(0xffffffffu, sum, o);
    float lse = m + logf(sum);
    float p = ex / sum;

    float accv = 0.f;
#pragma unroll
    for (int jj = 0; jj < 32; jj++) {
        float pj = __shfl_sync(0xffffffffu, p, jj);
        accv += pj * vv[jj][lane];
    }

    int n_i = nn[i], h_i = hh[i];
    g_o[((long)(bh * NH + h_i) * NPAD + n_i) * EDIM + lane] = accv;
    if (lane == 0) g_lse[(bh * NH + h_i) * NPAD + n_i] = lse;
}

// ---------------- combine hashes: softmax over per-hash lse -------------------
__global__ __launch_bounds__(256)
void combine_kernel()
{
    int gid  = blockIdx.x * blockDim.x + threadIdx.x;
    int wid  = gid >> 5;
    int lane = gid & 31;
    if (wid >= BH * NPAD) return;
    int bh = wid / NPAD;
    int n  = wid - bh * NPAD;

    float l0 = g_lse[(bh * NH + 0) * NPAD + n];
    float l1 = g_lse[(bh * NH + 1) * NPAD + n];
    float l2 = g_lse[(bh * NH + 2) * NPAD + n];
    float l3 = g_lse[(bh * NH + 3) * NPAD + n];
    float m = fmaxf(fmaxf(l0, l1), fmaxf(l2, l3));
    float e0 = expf(l0 - m), e1 = expf(l1 - m), e2 = expf(l2 - m), e3 = expf(l3 - m);
    float inv = 1.0f / (e0 + e1 + e2 + e3);

    float acc =
        e0 * inv * g_o[((long)(bh * NH + 0) * NPAD + n) * EDIM + lane] +
        e1 * inv * g_o[((long)(bh * NH + 1) * NPAD + n) * EDIM + lane] +
        e2 * inv * g_o[((long)(bh * NH + 2) * NPAD + n) * EDIM + lane] +
        e3 * inv * g_o[((long)(bh * NH + 3) * NPAD + n) * EDIM + lane];

    int b_l = bh >> 3, head = bh & 7;
    g_hcomb[(long)(b_l * NPAD + n) * D + head * EDIM + lane] = acc;
}

// ---------------- launch --------------------------------------------------------
extern "C" void kernel_launch(void* const* d_in, const int* in_sizes, int n_in,
                              void* d_out, int out_size)
{
    const float* x      = (const float*)d_in[0];
    const float* ste    = (const float*)d_in[1];
    const float* w_proj = (const float*)d_in[2];
    const float* b_proj = (const float*)d_in[3];
    const float* w_qk   = (const float*)d_in[4];
    const float* w_v    = (const float*)d_in[5];
    const float* w_out  = (const float*)d_in[6];
    const float* b_out  = (const float*)d_in[7];
    const float* rots   = (const float*)d_in[8];
    float* out = (float*)d_out;

    gemm_k<0><<<dim3(GRIDM, 2), 256>>>(x, ste, w_proj, nullptr, b_proj, nullptr);
    gemm_k<1><<<dim3(GRIDM, 4), 256>>>(nullptr, nullptr, w_qk, w_v, nullptr, nullptr);
    zero_pad_qkv<<<(BH * (NPAD - NVAL) * EDIM + 255) / 256, 256>>>();
    hash_kernel<<<(BH * NPAD + 255) / 256, 256>>>(rots);
    sort_kernel<<<BH, 128>>>();
    attn_kernel<<<dim3(NC, BH), 512>>>();
    combine_kernel<<<(BH * NPAD * 32) / 256, 256>>>();
    gemm_k<2><<<dim3(GRIDM, 2), 256>>>(nullptr, nullptr, w_out, nullptr, b_out, out);
}